// round 1
// baseline (speedup 1.0000x reference)
#include <cuda_runtime.h>
#include <cuda_bf16.h>

// Problem constants
#define BSZ   8
#define TLEN  4096
#define HDIM  1024
#define N3H   3072            // 3*H
#define KSZ   1024
#define MROWS (BSZ * TLEN)    // 32768

// Scratch: z buffer [M, 3H] and intermediate h [M, H] (device globals per rules)
__device__ float g_z[(size_t)MROWS * N3H];
__device__ float g_h[(size_t)MROWS * HDIM];

typedef unsigned long long ull;

// Packed f32x2 FMA: d.lo += a.lo*b.lo ; d.hi += a.hi*b.hi  (FFMA2 in SASS)
__device__ __forceinline__ void fma2(ull& d, ull a, ull b) {
    asm("fma.rn.f32x2 %0, %1, %2, %0;" : "+l"(d) : "l"(a), "l"(b));
}
// Broadcast-pack a scalar into both halves of an f32x2 register
__device__ __forceinline__ ull pack2(float x) {
    ull r; asm("mov.b64 %0, {%1, %1};" : "=l"(r) : "f"(x)); return r;
}

// ---------------------------------------------------------------------------
// GEMM: C[M,N] = A[M,K] * B[K,N], all fp32 row-major.
// 128x128 block tile, BK=8, 256 threads, 8x8 microtile (as 8x4 f32x2 pairs).
// ---------------------------------------------------------------------------
#define BM 128
#define BN 128
#define BK 8

__global__ void __launch_bounds__(256, 2)
gemm_f32x2_kernel(const float* __restrict__ A, const float* __restrict__ B,
                  float* __restrict__ C, int M, int N, int K)
{
    __shared__ __align__(16) float As[2][BK][BM];   // A stored transposed
    __shared__ __align__(16) float Bs[2][BK][BN];

    const int tid = threadIdx.x;
    const int tx  = tid & 15;          // 0..15  -> column group
    const int ty  = tid >> 4;          // 0..15  -> row group
    const int bm  = blockIdx.y * BM;
    const int bn  = blockIdx.x * BN;

    const float* Ab = A + (size_t)bm * K;
    const float* Bb = B + bn;

    // global-load assignment
    const int arow = tid >> 1;         // 0..127
    const int acol = (tid & 1) * 4;    // 0 or 4
    const int brow = tid >> 5;         // 0..7
    const int bcol = (tid & 31) * 4;   // 0..124

    // prologue: tile 0 -> smem[0]
    float4 ra = *(const float4*)(Ab + (size_t)arow * K + acol);
    float4 rb = *(const float4*)(Bb + (size_t)brow * N + bcol);
    As[0][acol + 0][arow] = ra.x;
    As[0][acol + 1][arow] = ra.y;
    As[0][acol + 2][arow] = ra.z;
    As[0][acol + 3][arow] = ra.w;
    *(float4*)&Bs[0][brow][bcol] = rb;
    __syncthreads();

    ull acc[8][4];
    #pragma unroll
    for (int i = 0; i < 8; i++)
        #pragma unroll
        for (int j = 0; j < 4; j++) acc[i][j] = 0ull;

    const int ktiles = K / BK;
    for (int kt = 0; kt < ktiles; ++kt) {
        const int cur = kt & 1;
        if (kt + 1 < ktiles) {
            const int k0 = (kt + 1) * BK;
            ra = *(const float4*)(Ab + (size_t)arow * K + k0 + acol);
            rb = *(const float4*)(Bb + (size_t)(k0 + brow) * N + bcol);
        }
        #pragma unroll
        for (int kk = 0; kk < BK; ++kk) {
            float4 a0 = *(const float4*)&As[cur][kk][ty * 8];
            float4 a1 = *(const float4*)&As[cur][kk][ty * 8 + 4];
            ull b2[4];
            #pragma unroll
            for (int j = 0; j < 4; j++)
                b2[j] = *(const ull*)&Bs[cur][kk][tx * 8 + 2 * j];
            float av[8] = {a0.x, a0.y, a0.z, a0.w, a1.x, a1.y, a1.z, a1.w};
            #pragma unroll
            for (int i = 0; i < 8; i++) {
                ull a2 = pack2(av[i]);
                #pragma unroll
                for (int j = 0; j < 4; j++) fma2(acc[i][j], a2, b2[j]);
            }
        }
        if (kt + 1 < ktiles) {
            const int nxt = cur ^ 1;
            As[nxt][acol + 0][arow] = ra.x;
            As[nxt][acol + 1][arow] = ra.y;
            As[nxt][acol + 2][arow] = ra.z;
            As[nxt][acol + 3][arow] = ra.w;
            *(float4*)&Bs[nxt][brow][bcol] = rb;
            __syncthreads();
        }
    }

    // epilogue: each acc holds two adjacent columns
    float* Cb = C + (size_t)bm * N + bn;
    #pragma unroll
    for (int i = 0; i < 8; i++) {
        float* crow = Cb + (size_t)(ty * 8 + i) * N + tx * 8;
        #pragma unroll
        for (int j = 0; j < 4; j++) {
            union { ull u; float2 f; } cv;
            cv.u = acc[i][j];
            *(float2*)(crow + 2 * j) = cv.f;
        }
    }
}

// ---------------------------------------------------------------------------
// Fused gates + sequential recurrence + highway.
// One thread per (batch, channel); coalesced across channels.
//   coeff = sigmoid(-gate); value = sigmoid(gate)*g(hidden)
//   s_t   = coeff*s_{t-1} + value
//   out_t = gp*s_t + (1-gp)*h_t,  gp = sigmoid(proj)
// ---------------------------------------------------------------------------
__global__ void __launch_bounds__(256)
scan_kernel(const float* __restrict__ z, const float* __restrict__ hin,
            float* __restrict__ hout)
{
    const int idx = blockIdx.x * blockDim.x + threadIdx.x;   // 0 .. B*H-1
    const int b = idx >> 10;             // / HDIM
    const int c = idx & (HDIM - 1);

    const float* zb = z   + (size_t)b * TLEN * N3H  + c;
    const float* hb = hin + (size_t)b * TLEN * HDIM + c;
    float*       ob = hout + (size_t)b * TLEN * HDIM + c;

    float s = 0.0f;
    #pragma unroll 4
    for (int t = 0; t < TLEN; ++t) {
        const size_t zoff = (size_t)t * N3H;
        const size_t hoff = (size_t)t * HDIM;
        float zh = zb[zoff];                 // hidden
        float zg = zb[zoff + HDIM];          // gate
        float zp = zb[zoff + 2 * HDIM];      // proj
        float h0 = hb[hoff];

        float sg    = 1.0f / (1.0f + __expf(-zg));   // sigmoid(gate)
        float coeff = 1.0f / (1.0f + __expf( zg));   // sigmoid(-gate) = 1-sg (stable)
        float gv    = (zh >= 0.0f) ? (zh + 0.5f)
                                   : (1.0f / (1.0f + __expf(-zh)));
        s = fmaf(coeff, s, sg * gv);

        float gp = 1.0f / (1.0f + __expf(-zp));
        ob[hoff] = fmaf(gp, s - h0, h0);     // gp*s + (1-gp)*h0
    }
}

// ---------------------------------------------------------------------------
extern "C" void kernel_launch(void* const* d_in, const int* in_sizes, int n_in,
                              void* d_out, int out_size)
{
    const float* h  = (const float*)d_in[0];
    const float* W0 = (const float*)d_in[1];
    const float* W1 = (const float*)d_in[2];
    float* out = (float*)d_out;

    float *zbuf, *hbuf;
    cudaGetSymbolAddress((void**)&zbuf, g_z);
    cudaGetSymbolAddress((void**)&hbuf, g_h);

    dim3 ggrid(N3H / BN, MROWS / BM);     // (24, 256)
    dim3 gblk(256);
    dim3 sgrid((BSZ * HDIM) / 256);       // 32
    dim3 sblk(256);

    // layer 0
    gemm_f32x2_kernel<<<ggrid, gblk>>>(h, W0, zbuf, MROWS, N3H, KSZ);
    scan_kernel<<<sgrid, sblk>>>(zbuf, h, hbuf);
    // layer 1
    gemm_f32x2_kernel<<<ggrid, gblk>>>(hbuf, W1, zbuf, MROWS, N3H, KSZ);
    scan_kernel<<<sgrid, sblk>>>(zbuf, hbuf, out);
}

// round 3
// speedup vs baseline: 3.5276x; 3.5276x over previous
#include <cuda_runtime.h>
#include <cuda_bf16.h>
#include <cstdint>

// ---------------------------------------------------------------------------
// Problem constants
// ---------------------------------------------------------------------------
#define BSZ   8
#define TLEN  4096
#define HDIM  1024
#define N3H   3072
#define KSZ   1024
#define MROWS (BSZ * TLEN)      // 32768
#define NC    32                // scan chunks per sequence
#define CL    (TLEN / NC)       // 128 steps per chunk

// ---------------------------------------------------------------------------
// Device scratch (no allocations allowed)
// ---------------------------------------------------------------------------
__device__ float         g_z [(size_t)MROWS * N3H];     // GEMM output z
__device__ float         g_h [(size_t)MROWS * HDIM];    // inter-layer h
__device__ __nv_bfloat16 g_ah[(size_t)MROWS * HDIM];    // A hi split
__device__ __nv_bfloat16 g_al[(size_t)MROWS * HDIM];    // A lo split
__device__ __nv_bfloat16 g_bh[(size_t)N3H * KSZ];       // W^T hi split [N,K]
__device__ __nv_bfloat16 g_bl[(size_t)N3H * KSZ];       // W^T lo split
__device__ float         g_cP[(size_t)BSZ * NC * HDIM]; // chunk coeff product
__device__ float         g_cS[(size_t)BSZ * NC * HDIM]; // chunk local scan end
__device__ float         g_pf[(size_t)BSZ * NC * HDIM]; // chunk carry-in

// ---------------------------------------------------------------------------
// Helpers
// ---------------------------------------------------------------------------
__device__ __forceinline__ uint32_t smem_u32(const void* p) {
    uint32_t a;
    asm("{ .reg .u64 t; cvta.to.shared.u64 t, %1; cvt.u32.u64 %0, t; }"
        : "=r"(a) : "l"(p));
    return a;
}

__device__ __forceinline__ void cp16(uint32_t dst, const void* src) {
    asm volatile("cp.async.cg.shared.global [%0], [%1], 16;" :: "r"(dst), "l"(src));
}

__device__ __forceinline__ void ldsm4(uint32_t r[4], uint32_t addr) {
    asm volatile("ldmatrix.sync.aligned.m8n8.x4.shared.b16 {%0,%1,%2,%3}, [%4];"
        : "=r"(r[0]), "=r"(r[1]), "=r"(r[2]), "=r"(r[3]) : "r"(addr));
}

__device__ __forceinline__ void mma16816(float c[4], const uint32_t a[4],
                                         uint32_t b0, uint32_t b1) {
    asm volatile(
        "mma.sync.aligned.m16n8k16.row.col.f32.bf16.bf16.f32 "
        "{%0,%1,%2,%3}, {%4,%5,%6,%7}, {%8,%9}, {%0,%1,%2,%3};"
        : "+f"(c[0]), "+f"(c[1]), "+f"(c[2]), "+f"(c[3])
        : "r"(a[0]), "r"(a[1]), "r"(a[2]), "r"(a[3]), "r"(b0), "r"(b1));
}

// ---------------------------------------------------------------------------
// GEMM: C[M,3H] = A[M,K] * W[K,3H], bf16 split:  Ah*Bh + Ah*Bl + Al*Bh
// B passed transposed ([N,K] K-major).
// Tile 128x128, BK=32, 4-stage cp.async pipe, 8 warps x (64x32) HMMA.
// ---------------------------------------------------------------------------
#define GM_BM 128
#define GM_BN 128
#define GM_BK 32
#define STAGES 4
#define KITERS (KSZ / GM_BK)                    // 32
#define OP_BYTES 8192                           // one operand tile (128x32 bf16)
#define STAGE_BYTES (4 * OP_BYTES)              // Ah, Al, Bh, Bl
#define SMEM_DYN (STAGES * STAGE_BYTES)         // 128 KB

// smem offset within an operand tile for (k16-slice, row, 16B-group)
__device__ __forceinline__ uint32_t sw_off(int slice, int r, int g) {
    return (uint32_t)(((slice * 128 + r) * 2 + (g ^ ((r >> 2) & 1))) * 16);
}

__device__ __forceinline__ void load_stage(
    uint32_t sbase, int stage,
    const __nv_bfloat16* __restrict__ Ah, const __nv_bfloat16* __restrict__ Al,
    const __nv_bfloat16* __restrict__ Bh, const __nv_bfloat16* __restrict__ Bl,
    int bm, int bn, int kt, int tid)
{
    const int k0 = kt * GM_BK;
    const uint32_t st = sbase + (uint32_t)stage * STAGE_BYTES;
    #pragma unroll
    for (int i = 0; i < 8; ++i) {
        int idx = tid + i * 256;                 // 0 .. 2047
        int op = idx >> 9;                       // 0=Ah 1=Al 2=Bh 3=Bl
        int j = idx & 511;
        int r = j >> 2, slice = (j >> 1) & 1, g = j & 1;
        const __nv_bfloat16* base = (op == 0) ? Ah : (op == 1) ? Al
                                  : (op == 2) ? Bh : Bl;
        int grow = ((op < 2) ? bm : bn) + r;
        const void* src = base + (size_t)grow * KSZ + k0 + slice * 16 + g * 8;
        cp16(st + (uint32_t)op * OP_BYTES + sw_off(slice, r, g), src);
    }
    asm volatile("cp.async.commit_group;" ::: "memory");
}

__global__ void __launch_bounds__(256, 1)
gemm_hmma(const __nv_bfloat16* __restrict__ Ah, const __nv_bfloat16* __restrict__ Al,
          const __nv_bfloat16* __restrict__ Bh, const __nv_bfloat16* __restrict__ Bl,
          float* __restrict__ C)
{
    extern __shared__ char dsm[];
    const uint32_t sbase = smem_u32(dsm);

    const int tid  = threadIdx.x;
    const int lane = tid & 31;
    const int wid  = tid >> 5;
    const int wm   = wid >> 2;                 // 0..1  (64-row slab)
    const int wn   = wid & 3;                  // 0..3  (32-col slab)
    const int bm   = blockIdx.y * GM_BM;
    const int bn   = blockIdx.x * GM_BN;

    // ldmatrix lane-address components
    const int rowA = (lane & 7) + ((lane >> 3) & 1) * 8;  // A: mat0 rows0-7,g0; mat1 rows8-15,g0; mat2/3 g1
    const int gA   = lane >> 4;
    const int rowB = (lane & 7) + (lane >> 4) * 8;        // B: mat0 n0-7,g0; mat1 n0-7,g1; mat2/3 n8-15
    const int gB   = (lane >> 3) & 1;

    float acc[4][4][4];
    #pragma unroll
    for (int i = 0; i < 4; ++i)
        #pragma unroll
        for (int j = 0; j < 4; ++j)
            #pragma unroll
            for (int q = 0; q < 4; ++q) acc[i][j][q] = 0.0f;

    // prologue: fill STAGES-1 stages
    #pragma unroll
    for (int s = 0; s < STAGES - 1; ++s)
        load_stage(sbase, s, Ah, Al, Bh, Bl, bm, bn, s, tid);

    for (int kt = 0; kt < KITERS; ++kt) {
        asm volatile("cp.async.wait_group %0;" :: "n"(STAGES - 2) : "memory");
        __syncthreads();

        // issue the next stage's loads (overlaps with compute below)
        if (kt + STAGES - 1 < KITERS)
            load_stage(sbase, (kt + STAGES - 1) & (STAGES - 1),
                       Ah, Al, Bh, Bl, bm, bn, kt + STAGES - 1, tid);

        const uint32_t st = sbase + (uint32_t)(kt & (STAGES - 1)) * STAGE_BYTES;

        #pragma unroll
        for (int slice = 0; slice < 2; ++slice) {
            uint32_t aH[4][4], aL[4][4], bH[2][4], bL[2][4];
            #pragma unroll
            for (int mf = 0; mf < 4; ++mf) {
                const uint32_t off = sw_off(slice, wm * 64 + mf * 16 + rowA, gA);
                ldsm4(aH[mf], st + 0 * OP_BYTES + off);
                ldsm4(aL[mf], st + 1 * OP_BYTES + off);
            }
            #pragma unroll
            for (int nf = 0; nf < 2; ++nf) {
                const uint32_t off = sw_off(slice, wn * 32 + nf * 16 + rowB, gB);
                ldsm4(bH[nf], st + 2 * OP_BYTES + off);
                ldsm4(bL[nf], st + 3 * OP_BYTES + off);
            }
            #pragma unroll
            for (int mf = 0; mf < 4; ++mf)
                #pragma unroll
                for (int n16 = 0; n16 < 2; ++n16)
                    #pragma unroll
                    for (int h = 0; h < 2; ++h) {
                        float* c = acc[mf][n16 * 2 + h];
                        mma16816(c, aH[mf], bH[n16][2 * h], bH[n16][2 * h + 1]);
                        mma16816(c, aH[mf], bL[n16][2 * h], bL[n16][2 * h + 1]);
                        mma16816(c, aL[mf], bH[n16][2 * h], bH[n16][2 * h + 1]);
                    }
        }
    }

    // epilogue: write C (fp32)
    #pragma unroll
    for (int mf = 0; mf < 4; ++mf) {
        const int row = bm + wm * 64 + mf * 16 + (lane >> 2);
        #pragma unroll
        for (int n16 = 0; n16 < 2; ++n16)
            #pragma unroll
            for (int h = 0; h < 2; ++h) {
                const float* c = acc[mf][n16 * 2 + h];
                const int col = bn + wn * 32 + n16 * 16 + h * 8 + (lane & 3) * 2;
                *(float2*)(C + (size_t)row * N3H + col)       = make_float2(c[0], c[1]);
                *(float2*)(C + (size_t)(row + 8) * N3H + col) = make_float2(c[2], c[3]);
            }
    }
}

// ---------------------------------------------------------------------------
// bf16 split of a dense fp32 array (A operand)
// ---------------------------------------------------------------------------
__global__ void __launch_bounds__(256)
split_h_kernel(const float* __restrict__ x, __nv_bfloat16* __restrict__ hi,
               __nv_bfloat16* __restrict__ lo)
{
    const size_t i = (size_t)blockIdx.x * blockDim.x + threadIdx.x;
    float4 v = ((const float4*)x)[i];
    __nv_bfloat16 h0 = __float2bfloat16(v.x), h1 = __float2bfloat16(v.y);
    __nv_bfloat16 h2 = __float2bfloat16(v.z), h3 = __float2bfloat16(v.w);
    __nv_bfloat162 H0(h0, h1), H1(h2, h3);
    __nv_bfloat162 L0(__float2bfloat16(v.x - __bfloat162float(h0)),
                      __float2bfloat16(v.y - __bfloat162float(h1)));
    __nv_bfloat162 L1(__float2bfloat16(v.z - __bfloat162float(h2)),
                      __float2bfloat16(v.w - __bfloat162float(h3)));
    ((__nv_bfloat162*)hi)[2 * i]     = H0;
    ((__nv_bfloat162*)hi)[2 * i + 1] = H1;
    ((__nv_bfloat162*)lo)[2 * i]     = L0;
    ((__nv_bfloat162*)lo)[2 * i + 1] = L1;
}

// ---------------------------------------------------------------------------
// transpose + bf16 split of W:  W[K,3H] -> Wt_hi/lo[3H,K]
// ---------------------------------------------------------------------------
__global__ void __launch_bounds__(256)
split_wt_kernel(const float* __restrict__ W, __nv_bfloat16* __restrict__ th,
                __nv_bfloat16* __restrict__ tl)
{
    __shared__ float tile[32][33];
    const int n0 = blockIdx.x * 32;
    const int k0 = blockIdx.y * 32;
    const int tx = threadIdx.x, ty = threadIdx.y;   // 32 x 8
    #pragma unroll
    for (int r = ty; r < 32; r += 8)
        tile[r][tx] = W[(size_t)(k0 + r) * N3H + n0 + tx];
    __syncthreads();
    #pragma unroll
    for (int r = ty; r < 32; r += 8) {
        float v = tile[tx][r];                      // = W[k0+tx][n0+r]
        __nv_bfloat16 hi = __float2bfloat16(v);
        size_t o = (size_t)(n0 + r) * KSZ + k0 + tx;
        th[o] = hi;
        tl[o] = __float2bfloat16(v - __bfloat162float(hi));
    }
}

// ---------------------------------------------------------------------------
// Scan phase 1: per (b, chunk, c): P = prod coeff, S = chunk-local scan end
// ---------------------------------------------------------------------------
__global__ void __launch_bounds__(256)
scan_p1(const float* __restrict__ z, float* __restrict__ cP, float* __restrict__ cS)
{
    const int idx = blockIdx.x * blockDim.x + threadIdx.x;   // B*NC*H
    const int c = idx & (HDIM - 1);
    const int chunk = (idx >> 10) & (NC - 1);
    const int b = idx >> 15;
    const float* zb = z + ((size_t)b * TLEN + (size_t)chunk * CL) * N3H + c;
    float P = 1.0f, S = 0.0f;
    #pragma unroll 4
    for (int t = 0; t < CL; ++t) {
        float zh = zb[(size_t)t * N3H];
        float zg = zb[(size_t)t * N3H + HDIM];
        float sg = 1.0f / (1.0f + __expf(-zg));
        float cf = 1.0f / (1.0f + __expf(zg));
        float gv = (zh >= 0.0f) ? (zh + 0.5f) : 1.0f / (1.0f + __expf(-zh));
        S = fmaf(cf, S, sg * gv);
        P *= cf;
    }
    cP[idx] = P;
    cS[idx] = S;
}

// ---------------------------------------------------------------------------
// Scan phase 2: sequential combine over chunks -> carry-in per chunk
// ---------------------------------------------------------------------------
__global__ void __launch_bounds__(256)
scan_p2(const float* __restrict__ cP, const float* __restrict__ cS, float* __restrict__ pf)
{
    const int idx = blockIdx.x * blockDim.x + threadIdx.x;   // B*H
    const int c = idx & (HDIM - 1);
    const int b = idx >> 10;
    float s = 0.0f;
    #pragma unroll
    for (int j = 0; j < NC; ++j) {
        size_t o = ((size_t)(b * NC + j) << 10) + c;
        pf[o] = s;
        s = fmaf(cP[o], s, cS[o]);
    }
}

// ---------------------------------------------------------------------------
// Scan phase 3: replay chunk with carry-in, highway gate, write outputs
// (optionally also write bf16 split of output for next layer's GEMM A)
// ---------------------------------------------------------------------------
__global__ void __launch_bounds__(256)
scan_p3(const float* __restrict__ z, const float* __restrict__ hin,
        const float* __restrict__ pf, float* __restrict__ hout,
        __nv_bfloat16* __restrict__ ohi, __nv_bfloat16* __restrict__ olo, int wsplit)
{
    const int idx = blockIdx.x * blockDim.x + threadIdx.x;
    const int c = idx & (HDIM - 1);
    const int chunk = (idx >> 10) & (NC - 1);
    const int b = idx >> 15;
    const size_t row0 = (size_t)b * TLEN + (size_t)chunk * CL;
    const float* zb = z + row0 * N3H + c;
    const float* hb = hin + row0 * HDIM + c;
    float* ob = hout + row0 * HDIM + c;

    float s = pf[idx];
    #pragma unroll 4
    for (int t = 0; t < CL; ++t) {
        float zh = zb[(size_t)t * N3H];
        float zg = zb[(size_t)t * N3H + HDIM];
        float zp = zb[(size_t)t * N3H + 2 * HDIM];
        float h0 = hb[(size_t)t * HDIM];
        float sg = 1.0f / (1.0f + __expf(-zg));
        float cf = 1.0f / (1.0f + __expf(zg));
        float gv = (zh >= 0.0f) ? (zh + 0.5f) : 1.0f / (1.0f + __expf(-zh));
        s = fmaf(cf, s, sg * gv);
        float gp = 1.0f / (1.0f + __expf(-zp));
        float out = fmaf(gp, s - h0, h0);
        ob[(size_t)t * HDIM] = out;
        if (wsplit) {
            __nv_bfloat16 hi = __float2bfloat16(out);
            size_t o = row0 * HDIM + (size_t)t * HDIM + c;
            ohi[o] = hi;
            olo[o] = __float2bfloat16(out - __bfloat162float(hi));
        }
    }
}

// ---------------------------------------------------------------------------
extern "C" void kernel_launch(void* const* d_in, const int* in_sizes, int n_in,
                              void* d_out, int out_size)
{
    const float* h  = (const float*)d_in[0];
    const float* W0 = (const float*)d_in[1];
    const float* W1 = (const float*)d_in[2];
    float* out = (float*)d_out;

    float *zbuf, *hbuf, *cP, *cS, *pf;
    __nv_bfloat16 *ah, *al, *bh, *bl;
    cudaGetSymbolAddress((void**)&zbuf, g_z);
    cudaGetSymbolAddress((void**)&hbuf, g_h);
    cudaGetSymbolAddress((void**)&ah, g_ah);
    cudaGetSymbolAddress((void**)&al, g_al);
    cudaGetSymbolAddress((void**)&bh, g_bh);
    cudaGetSymbolAddress((void**)&bl, g_bl);
    cudaGetSymbolAddress((void**)&cP, g_cP);
    cudaGetSymbolAddress((void**)&cS, g_cS);
    cudaGetSymbolAddress((void**)&pf, g_pf);

    cudaFuncSetAttribute(gemm_hmma,
                         cudaFuncAttributeMaxDynamicSharedMemorySize, SMEM_DYN);

    const dim3 ggrid(N3H / GM_BN, MROWS / GM_BM);        // (24, 256)
    const int p1_blocks = (BSZ * NC * HDIM) / 256;       // 1024
    const int p2_blocks = (BSZ * HDIM) / 256;            // 32
    const int sh_blocks = (MROWS * HDIM / 4) / 256;      // 32768
    const dim3 wt_grid(N3H / 32, KSZ / 32);              // (96, 32)
    const dim3 wt_blk(32, 8);

    // ---- layer 0 ----
    split_wt_kernel<<<wt_grid, wt_blk>>>(W0, bh, bl);
    split_h_kernel<<<sh_blocks, 256>>>(h, ah, al);
    gemm_hmma<<<ggrid, 256, SMEM_DYN>>>(ah, al, bh, bl, zbuf);
    scan_p1<<<p1_blocks, 256>>>(zbuf, cP, cS);
    scan_p2<<<p2_blocks, 256>>>(cP, cS, pf);
    scan_p3<<<p1_blocks, 256>>>(zbuf, h, pf, hbuf, ah, al, 1);

    // ---- layer 1 ----
    split_wt_kernel<<<wt_grid, wt_blk>>>(W1, bh, bl);
    gemm_hmma<<<ggrid, 256, SMEM_DYN>>>(ah, al, bh, bl, zbuf);
    scan_p1<<<p1_blocks, 256>>>(zbuf, cP, cS);
    scan_p2<<<p2_blocks, 256>>>(cP, cS, pf);
    scan_p3<<<p1_blocks, 256>>>(zbuf, hbuf, pf, out, (__nv_bfloat16*)0, (__nv_bfloat16*)0, 0);
}

// round 4
// speedup vs baseline: 3.8989x; 1.1052x over previous
#include <cuda_runtime.h>
#include <cuda_bf16.h>
#include <cstdint>

// ---------------------------------------------------------------------------
// Problem constants
// ---------------------------------------------------------------------------
#define BSZ   8
#define TLEN  4096
#define HDIM  1024
#define N3H   3072
#define KSZ   1024
#define MROWS (BSZ * TLEN)      // 32768
#define NC    32                // scan chunks per sequence
#define CL    (TLEN / NC)       // 128 steps per chunk

// ---------------------------------------------------------------------------
// Device scratch (no allocations allowed)
// ---------------------------------------------------------------------------
__device__ float         g_z [(size_t)MROWS * N3H];     // GEMM output z
__device__ float         g_h [(size_t)MROWS * HDIM];    // inter-layer h
__device__ __nv_bfloat16 g_ah[(size_t)MROWS * HDIM];    // A hi split
__device__ __nv_bfloat16 g_al[(size_t)MROWS * HDIM];    // A lo split
__device__ __nv_bfloat16 g_bh[(size_t)N3H * KSZ];       // W^T hi split [N,K]
__device__ __nv_bfloat16 g_bl[(size_t)N3H * KSZ];       // W^T lo split
__device__ float         g_cP[(size_t)BSZ * NC * HDIM]; // chunk coeff product
__device__ float         g_cS[(size_t)BSZ * NC * HDIM]; // chunk local scan end
__device__ float         g_pf[(size_t)BSZ * NC * HDIM]; // chunk carry-in

// ---------------------------------------------------------------------------
// Helpers
// ---------------------------------------------------------------------------
__device__ __forceinline__ uint32_t smem_u32(const void* p) {
    uint32_t a;
    asm("{ .reg .u64 t; cvta.to.shared.u64 t, %1; cvt.u32.u64 %0, t; }"
        : "=r"(a) : "l"(p));
    return a;
}

__device__ __forceinline__ void cp16(uint32_t dst, const void* src) {
    asm volatile("cp.async.cg.shared.global [%0], [%1], 16;" :: "r"(dst), "l"(src));
}

__device__ __forceinline__ void ldsm4(uint32_t r[4], uint32_t addr) {
    asm volatile("ldmatrix.sync.aligned.m8n8.x4.shared.b16 {%0,%1,%2,%3}, [%4];"
        : "=r"(r[0]), "=r"(r[1]), "=r"(r[2]), "=r"(r[3]) : "r"(addr));
}

__device__ __forceinline__ void mma16816(float c[4], const uint32_t a[4],
                                         uint32_t b0, uint32_t b1) {
    asm volatile(
        "mma.sync.aligned.m16n8k16.row.col.f32.bf16.bf16.f32 "
        "{%0,%1,%2,%3}, {%4,%5,%6,%7}, {%8,%9}, {%0,%1,%2,%3};"
        : "+f"(c[0]), "+f"(c[1]), "+f"(c[2]), "+f"(c[3])
        : "r"(a[0]), "r"(a[1]), "r"(a[2]), "r"(a[3]), "r"(b0), "r"(b1));
}

// fast sigmoid pieces
__device__ __forceinline__ float fsig(float x) {        // sigmoid(x)
    return __fdividef(1.0f, 1.0f + __expf(-x));
}

// ---------------------------------------------------------------------------
// GEMM: C[M,3H] = A[M,K] * W[K,3H], bf16 split:  Ah*Bh + Ah*Bl + Al*Bh
// B passed transposed ([N,K] K-major).
// Tile 128x256, BK=32, 4-stage cp.async pipe, 8 warps x (64x64) HMMA.
// ---------------------------------------------------------------------------
#define GM_BM 128
#define GM_BN 256
#define GM_BK 32
#define STAGES 4
#define KITERS (KSZ / GM_BK)                    // 32
#define A_OP_BYTES 8192                         // 128x32 bf16
#define B_OP_BYTES 16384                        // 256x32 bf16
#define STAGE_BYTES (2 * A_OP_BYTES + 2 * B_OP_BYTES)   // 48 KB
#define SMEM_DYN (STAGES * STAGE_BYTES)         // 192 KB

// smem offset within an operand tile for (k16-slice, row, 16B-group)
__device__ __forceinline__ uint32_t sw_off(int slice, int r, int g, int rows) {
    return (uint32_t)(((slice * rows + r) * 2 + (g ^ ((r >> 2) & 1))) * 16);
}

__device__ __forceinline__ void load_stage(
    uint32_t sbase, int stage,
    const __nv_bfloat16* __restrict__ Ah, const __nv_bfloat16* __restrict__ Al,
    const __nv_bfloat16* __restrict__ Bh, const __nv_bfloat16* __restrict__ Bl,
    int bm, int bn, int kt, int tid)
{
    const int k0 = kt * GM_BK;
    const uint32_t st = sbase + (uint32_t)stage * STAGE_BYTES;
    #pragma unroll
    for (int i = 0; i < 12; ++i) {
        const int idx = tid + i * 256;          // 0 .. 3071
        const __nv_bfloat16* base;
        uint32_t off; int j, rows, grow;
        if (idx < 512)        { base = Ah; off = 0;                        j = idx;        rows = 128; grow = bm; }
        else if (idx < 1024)  { base = Al; off = A_OP_BYTES;               j = idx - 512;  rows = 128; grow = bm; }
        else if (idx < 2048)  { base = Bh; off = 2 * A_OP_BYTES;           j = idx - 1024; rows = 256; grow = bn; }
        else                  { base = Bl; off = 2 * A_OP_BYTES + B_OP_BYTES; j = idx - 2048; rows = 256; grow = bn; }
        const int r = j >> 2, slice = (j >> 1) & 1, g = j & 1;
        const void* src = base + (size_t)(grow + r) * KSZ + k0 + slice * 16 + g * 8;
        cp16(st + off + sw_off(slice, r, g, rows), src);
    }
    asm volatile("cp.async.commit_group;" ::: "memory");
}

__global__ void __launch_bounds__(256, 1)
gemm_hmma(const __nv_bfloat16* __restrict__ Ah, const __nv_bfloat16* __restrict__ Al,
          const __nv_bfloat16* __restrict__ Bh, const __nv_bfloat16* __restrict__ Bl,
          float* __restrict__ C)
{
    extern __shared__ char dsm[];
    const uint32_t sbase = smem_u32(dsm);

    const int tid  = threadIdx.x;
    const int lane = tid & 31;
    const int wid  = tid >> 5;
    const int wm   = wid >> 2;                 // 0..1  (64-row slab)
    const int wn   = wid & 3;                  // 0..3  (64-col slab)
    const int bm   = blockIdx.y * GM_BM;
    const int bn   = blockIdx.x * GM_BN;

    // ldmatrix lane-address components
    const int rowA = (lane & 7) + ((lane >> 3) & 1) * 8;
    const int gA   = lane >> 4;
    const int rowB = (lane & 7) + (lane >> 4) * 8;
    const int gB   = (lane >> 3) & 1;

    float acc[4][8][4];
    #pragma unroll
    for (int i = 0; i < 4; ++i)
        #pragma unroll
        for (int j = 0; j < 8; ++j)
            #pragma unroll
            for (int q = 0; q < 4; ++q) acc[i][j][q] = 0.0f;

    #pragma unroll
    for (int s = 0; s < STAGES - 1; ++s)
        load_stage(sbase, s, Ah, Al, Bh, Bl, bm, bn, s, tid);

    for (int kt = 0; kt < KITERS; ++kt) {
        asm volatile("cp.async.wait_group %0;" :: "n"(STAGES - 2) : "memory");
        __syncthreads();

        if (kt + STAGES - 1 < KITERS)
            load_stage(sbase, (kt + STAGES - 1) & (STAGES - 1),
                       Ah, Al, Bh, Bl, bm, bn, kt + STAGES - 1, tid);

        const uint32_t st = sbase + (uint32_t)(kt & (STAGES - 1)) * STAGE_BYTES;

        #pragma unroll
        for (int slice = 0; slice < 2; ++slice) {
            uint32_t aH[4][4], aL[4][4];
            #pragma unroll
            for (int mf = 0; mf < 4; ++mf) {
                const uint32_t off = sw_off(slice, wm * 64 + mf * 16 + rowA, gA, 128);
                ldsm4(aH[mf], st + off);
                ldsm4(aL[mf], st + A_OP_BYTES + off);
            }
            #pragma unroll
            for (int n16 = 0; n16 < 4; ++n16) {
                uint32_t bh4[4], bl4[4];
                const uint32_t offB = sw_off(slice, wn * 64 + n16 * 16 + rowB, gB, 256);
                ldsm4(bh4, st + 2 * A_OP_BYTES + offB);
                ldsm4(bl4, st + 2 * A_OP_BYTES + B_OP_BYTES + offB);
                #pragma unroll
                for (int mf = 0; mf < 4; ++mf)
                    #pragma unroll
                    for (int h = 0; h < 2; ++h) {
                        float* c = acc[mf][n16 * 2 + h];
                        mma16816(c, aH[mf], bh4[2 * h], bh4[2 * h + 1]);
                        mma16816(c, aH[mf], bl4[2 * h], bl4[2 * h + 1]);
                        mma16816(c, aL[mf], bh4[2 * h], bh4[2 * h + 1]);
                    }
            }
        }
    }

    // epilogue
    #pragma unroll
    for (int mf = 0; mf < 4; ++mf) {
        const int row = bm + wm * 64 + mf * 16 + (lane >> 2);
        #pragma unroll
        for (int nf = 0; nf < 8; ++nf) {
            const float* c = acc[mf][nf];
            const int col = bn + wn * 64 + nf * 8 + (lane & 3) * 2;
            *(float2*)(C + (size_t)row * N3H + col)       = make_float2(c[0], c[1]);
            *(float2*)(C + (size_t)(row + 8) * N3H + col) = make_float2(c[2], c[3]);
        }
    }
}

// ---------------------------------------------------------------------------
// bf16 split of a dense fp32 array (A operand)
// ---------------------------------------------------------------------------
__global__ void __launch_bounds__(256)
split_h_kernel(const float* __restrict__ x, __nv_bfloat16* __restrict__ hi,
               __nv_bfloat16* __restrict__ lo)
{
    const size_t i = (size_t)blockIdx.x * blockDim.x + threadIdx.x;
    float4 v = ((const float4*)x)[i];
    __nv_bfloat16 h0 = __float2bfloat16(v.x), h1 = __float2bfloat16(v.y);
    __nv_bfloat16 h2 = __float2bfloat16(v.z), h3 = __float2bfloat16(v.w);
    __nv_bfloat162 H0(h0, h1), H1(h2, h3);
    __nv_bfloat162 L0(__float2bfloat16(v.x - __bfloat162float(h0)),
                      __float2bfloat16(v.y - __bfloat162float(h1)));
    __nv_bfloat162 L1(__float2bfloat16(v.z - __bfloat162float(h2)),
                      __float2bfloat16(v.w - __bfloat162float(h3)));
    ((__nv_bfloat162*)hi)[2 * i]     = H0;
    ((__nv_bfloat162*)hi)[2 * i + 1] = H1;
    ((__nv_bfloat162*)lo)[2 * i]     = L0;
    ((__nv_bfloat162*)lo)[2 * i + 1] = L1;
}

// ---------------------------------------------------------------------------
// transpose + bf16 split of W:  W[K,3H] -> Wt_hi/lo[3H,K]
// ---------------------------------------------------------------------------
__global__ void __launch_bounds__(256)
split_wt_kernel(const float* __restrict__ W, __nv_bfloat16* __restrict__ th,
                __nv_bfloat16* __restrict__ tl)
{
    __shared__ float tile[32][33];
    const int n0 = blockIdx.x * 32;
    const int k0 = blockIdx.y * 32;
    const int tx = threadIdx.x, ty = threadIdx.y;   // 32 x 8
    #pragma unroll
    for (int r = ty; r < 32; r += 8)
        tile[r][tx] = W[(size_t)(k0 + r) * N3H + n0 + tx];
    __syncthreads();
    #pragma unroll
    for (int r = ty; r < 32; r += 8) {
        float v = tile[tx][r];                      // = W[k0+tx][n0+r]
        __nv_bfloat16 hi = __float2bfloat16(v);
        size_t o = (size_t)(n0 + r) * KSZ + k0 + tx;
        th[o] = hi;
        tl[o] = __float2bfloat16(v - __bfloat162float(hi));
    }
}

// ---------------------------------------------------------------------------
// Scan phase 1: per (b, chunk, c): P = prod coeff, S = chunk-local scan end
// ---------------------------------------------------------------------------
__global__ void __launch_bounds__(256)
scan_p1(const float* __restrict__ z, float* __restrict__ cP, float* __restrict__ cS)
{
    const int idx = blockIdx.x * blockDim.x + threadIdx.x;   // B*NC*H
    const int c = idx & (HDIM - 1);
    const int chunk = (idx >> 10) & (NC - 1);
    const int b = idx >> 15;
    const float* zb = z + ((size_t)b * TLEN + (size_t)chunk * CL) * N3H + c;
    float P = 1.0f, S = 0.0f;
    #pragma unroll 8
    for (int t = 0; t < CL; ++t) {
        float zh = __ldcs(zb + (size_t)t * N3H);
        float zg = __ldcs(zb + (size_t)t * N3H + HDIM);
        float e  = __expf(zg);
        float cf = __fdividef(1.0f, 1.0f + e);       // sigmoid(-zg)
        float sg = 1.0f - cf;                        // sigmoid(zg)
        float gv = (zh >= 0.0f) ? (zh + 0.5f) : fsig(zh);
        S = fmaf(cf, S, sg * gv);
        P *= cf;
    }
    cP[idx] = P;
    cS[idx] = S;
}

// ---------------------------------------------------------------------------
// Scan phase 2: sequential combine over chunks -> carry-in per chunk
// ---------------------------------------------------------------------------
__global__ void __launch_bounds__(256)
scan_p2(const float* __restrict__ cP, const float* __restrict__ cS, float* __restrict__ pf)
{
    const int idx = blockIdx.x * blockDim.x + threadIdx.x;   // B*H
    const int c = idx & (HDIM - 1);
    const int b = idx >> 10;
    float s = 0.0f;
    #pragma unroll
    for (int j = 0; j < NC; ++j) {
        size_t o = ((size_t)(b * NC + j) << 10) + c;
        pf[o] = s;
        s = fmaf(cP[o], s, cS[o]);
    }
}

// ---------------------------------------------------------------------------
// Scan phase 3: replay chunk with carry-in, highway gate, write outputs
// (optionally also write bf16 split of output for next layer's GEMM A)
// ---------------------------------------------------------------------------
__global__ void __launch_bounds__(256)
scan_p3(const float* __restrict__ z, const float* __restrict__ hin,
        const float* __restrict__ pf, float* __restrict__ hout,
        __nv_bfloat16* __restrict__ ohi, __nv_bfloat16* __restrict__ olo, int wsplit)
{
    const int idx = blockIdx.x * blockDim.x + threadIdx.x;
    const int c = idx & (HDIM - 1);
    const int chunk = (idx >> 10) & (NC - 1);
    const int b = idx >> 15;
    const size_t row0 = (size_t)b * TLEN + (size_t)chunk * CL;
    const float* zb = z + row0 * N3H + c;
    const float* hb = hin + row0 * HDIM + c;
    float* ob = hout + row0 * HDIM + c;

    float s = pf[idx];
    #pragma unroll 4
    for (int t = 0; t < CL; ++t) {
        float zh = __ldcs(zb + (size_t)t * N3H);
        float zg = __ldcs(zb + (size_t)t * N3H + HDIM);
        float zp = __ldcs(zb + (size_t)t * N3H + 2 * HDIM);
        float h0 = hb[(size_t)t * HDIM];
        float e  = __expf(zg);
        float cf = __fdividef(1.0f, 1.0f + e);
        float sg = 1.0f - cf;
        float gv = (zh >= 0.0f) ? (zh + 0.5f) : fsig(zh);
        s = fmaf(cf, s, sg * gv);
        float gp = fsig(zp);
        float out = fmaf(gp, s - h0, h0);
        ob[(size_t)t * HDIM] = out;
        if (wsplit) {
            __nv_bfloat16 hi = __float2bfloat16(out);
            size_t o = row0 * HDIM + (size_t)t * HDIM + c;
            ohi[o] = hi;
            olo[o] = __float2bfloat16(out - __bfloat162float(hi));
        }
    }
}

// ---------------------------------------------------------------------------
extern "C" void kernel_launch(void* const* d_in, const int* in_sizes, int n_in,
                              void* d_out, int out_size)
{
    const float* h  = (const float*)d_in[0];
    const float* W0 = (const float*)d_in[1];
    const float* W1 = (const float*)d_in[2];
    float* out = (float*)d_out;

    float *zbuf, *hbuf, *cP, *cS, *pf;
    __nv_bfloat16 *ah, *al, *bh, *bl;
    cudaGetSymbolAddress((void**)&zbuf, g_z);
    cudaGetSymbolAddress((void**)&hbuf, g_h);
    cudaGetSymbolAddress((void**)&ah, g_ah);
    cudaGetSymbolAddress((void**)&al, g_al);
    cudaGetSymbolAddress((void**)&bh, g_bh);
    cudaGetSymbolAddress((void**)&bl, g_bl);
    cudaGetSymbolAddress((void**)&cP, g_cP);
    cudaGetSymbolAddress((void**)&cS, g_cS);
    cudaGetSymbolAddress((void**)&pf, g_pf);

    cudaFuncSetAttribute(gemm_hmma,
                         cudaFuncAttributeMaxDynamicSharedMemorySize, SMEM_DYN);

    const dim3 ggrid(N3H / GM_BN, MROWS / GM_BM);        // (12, 256)
    const int p1_blocks = (BSZ * NC * HDIM) / 256;       // 1024
    const int p2_blocks = (BSZ * HDIM) / 256;            // 32
    const int sh_blocks = (MROWS * HDIM / 4) / 256;      // 32768
    const dim3 wt_grid(N3H / 32, KSZ / 32);              // (96, 32)
    const dim3 wt_blk(32, 8);

    // ---- layer 0 ----
    split_wt_kernel<<<wt_grid, wt_blk>>>(W0, bh, bl);
    split_h_kernel<<<sh_blocks, 256>>>(h, ah, al);
    gemm_hmma<<<ggrid, 256, SMEM_DYN>>>(ah, al, bh, bl, zbuf);
    scan_p1<<<p1_blocks, 256>>>(zbuf, cP, cS);
    scan_p2<<<p2_blocks, 256>>>(cP, cS, pf);
    scan_p3<<<p1_blocks, 256>>>(zbuf, h, pf, hbuf, ah, al, 1);

    // ---- layer 1 ----
    split_wt_kernel<<<wt_grid, wt_blk>>>(W1, bh, bl);
    gemm_hmma<<<ggrid, 256, SMEM_DYN>>>(ah, al, bh, bl, zbuf);
    scan_p1<<<p1_blocks, 256>>>(zbuf, cP, cS);
    scan_p2<<<p2_blocks, 256>>>(cP, cS, pf);
    scan_p3<<<p1_blocks, 256>>>(zbuf, hbuf, pf, out, (__nv_bfloat16*)0, (__nv_bfloat16*)0, 0);
}